// round 6
// baseline (speedup 1.0000x reference)
#include <cuda_runtime.h>
#include <cuda_bf16.h>
#include <cstdint>

// Problem constants (reference: TRACK_SIZE=16, C=240 -> 15 tracks).
#define C_TOT   240
#define ROW_F4  60          // float4 per row
#define TJ      64          // input rows per CTA tile
#define TY      8           // blockDim.y
#define KB      4           // rows per register batch
#define NB      2           // batches (TJ = TY*KB*NB)

// Input-major scatter: CTA reads input rows [r0, r0+64) fully coalesced
// (each useful byte read from DRAM exactly once; rows >= L skipped),
// then scatters each 16B chunk to its 1-3 output positions.
// Forward map: out[j] = x[((j+shift_t)%P)%L]; inverse: for vv in
// {r, r+L, r+2L} with vv<P: j = vv-shift (and j+P for the P-wrap case).
__global__ __launch_bounds__(480, 4) void rc_scatter_kernel(
    const float4* __restrict__ x,       // (B, N, 60) float4
    const int*    __restrict__ lengths, // (B,)
    float4*       __restrict__ out,     // (B, max_len, 60) float4
    int B, int N, int max_len)
{
    __shared__ int s_P, s_L;
    const int b  = blockIdx.z;
    const int r0 = blockIdx.x * TJ;

    if (threadIdx.x == 0 && threadIdx.y == 0) {
        int m = __ldg(lengths);
        #pragma unroll 4
        for (int i = 1; i < B; ++i) m = min(m, __ldg(lengths + i));
        s_P = 3 * m;
        s_L = __ldg(lengths + b);
    }
    __syncthreads();
    const int P = s_P;
    const int L = s_L;
    if (r0 >= L) return;                 // rows >= L are never used

    const int q  = threadIdx.x;          // 0..59 : float4 column
    const int ty = threadIdx.y;          // 0..7
    const int shift = (1u << (q >> 2)) >> 1;   // 0,1,2,4,...,2^13

    // P-wrap stores are dead unless P - shift < max_len (uniform per thread).
    const bool need_wrap = (P - shift) < max_len;

    const float4* __restrict__ src = x + ((size_t)b * N + r0) * ROW_F4 + q;
    float4* __restrict__ dst = out + (size_t)b * max_len * ROW_F4 + q;

    #pragma unroll
    for (int h = 0; h < NB; ++h) {
        // Phase 1: fully-coalesced sequential reads (evict-first, zero reuse).
        float4 v[KB];
        int    rr[KB];
        #pragma unroll
        for (int k = 0; k < KB; ++k) {
            const int rl = h * (TY * KB) + ty + TY * k;
            rr[k] = r0 + rl;
            if (rr[k] < L)
                v[k] = __ldcs(src + (size_t)rl * ROW_F4);
        }

        // Phase 2: scatter each chunk to its output positions.
        #pragma unroll
        for (int k = 0; k < KB; ++k) {
            const int r = rr[k];
            if (r >= L) continue;
            #pragma unroll
            for (int m = 0; m < 3; ++m) {
                const int vv = r + m * L;
                if (vv < P) {
                    const int j = vv - shift;
                    if (j >= 0 && j < max_len)
                        dst[(size_t)j * ROW_F4] = v[k];
                    if (need_wrap) {
                        const int j2 = j + P;
                        if (j2 >= 0 && j2 < max_len)
                            dst[(size_t)j2 * ROW_F4] = v[k];
                    }
                }
            }
        }
    }
}

extern "C" void kernel_launch(void* const* d_in, const int* in_sizes, int n_in,
                              void* d_out, int out_size) {
    const float* x       = (const float*)d_in[0];
    const int*   lengths = (const int*)d_in[1];
    float*       out     = (float*)d_out;

    const int B = in_sizes[1];                    // 8
    const int N = in_sizes[0] / (B * C_TOT);      // 16384
    const int max_len = out_size / (B * C_TOT);   // max(lengths)

    dim3 blk(ROW_F4, TY, 1);                      // 480 threads
    dim3 grid((N + TJ - 1) / TJ, 1, B);           // (256,1,8); tail CTAs exit
    rc_scatter_kernel<<<grid, blk>>>((const float4*)x, lengths, (float4*)out,
                                     B, N, max_len);
}

// round 7
// speedup vs baseline: 1.0555x; 1.0555x over previous
#include <cuda_runtime.h>
#include <cuda_bf16.h>
#include <cstdint>

// Problem constants (reference: TRACK_SIZE=16, C=240 -> 15 tracks).
#define C_TOT   240
#define ROW_F4  60          // float4 per row
#define TJ      32          // input rows per CTA tile
#define TY      8           // blockDim.y
#define KPT     (TJ / TY)   // rows per thread (4)

// Input-major scatter (R5 structure, proven fastest): CTA reads input rows
// [r0, r0+32) fully coalesced (each useful byte read once; rows >= L
// skipped), then scatters each 16B chunk to its 1-3 output positions.
// Stores are evict-first (__stcs) so the output stream does not evict the
// L2-resident portions of x (L2 = 126 MB ~ sizeof(x)).
// Forward map: out[j] = x[((j+shift_t)%P)%L]; inverse: for vv in
// {r, r+L, r+2L} with vv<P: j = vv-shift (and j+P for the P-wrap case).
__global__ __launch_bounds__(480, 4) void rc_scatter_kernel(
    const float4* __restrict__ x,       // (B, N, 60) float4
    const int*    __restrict__ lengths, // (B,)
    float4*       __restrict__ out,     // (B, max_len, 60) float4
    int B, int N, int max_len)
{
    const int b  = blockIdx.z;
    const int L  = __ldg(lengths + b);
    const int r0 = blockIdx.x * TJ;
    if (r0 >= L) return;                 // rows >= L are never used

    // min(lengths): B tiny; L1-hit broadcast loads, effectively free.
    int minL = __ldg(lengths);
    #pragma unroll 4
    for (int i = 1; i < B; ++i) minL = min(minL, __ldg(lengths + i));
    const int P = 3 * minL;

    const int q  = threadIdx.x;          // 0..59 : float4 column
    const int ty = threadIdx.y;          // 0..7
    const int shift = (1u << (q >> 2)) >> 1;   // 0,1,2,4,...,2^13

    const float4* __restrict__ src = x + ((size_t)b * N + r0) * ROW_F4 + q;
    float4* __restrict__ dst = out + (size_t)b * max_len * ROW_F4 + q;

    // Phase 1: fully-coalesced sequential reads.
    float4 v[KPT];
    int    rr[KPT];
    #pragma unroll
    for (int k = 0; k < KPT; ++k) {
        const int rl = ty + TY * k;
        rr[k] = r0 + rl;
        if (rr[k] < L)
            v[k] = __ldg(src + (size_t)rl * ROW_F4);
    }

    // Phase 2: scatter each chunk to its output positions (evict-first).
    #pragma unroll
    for (int k = 0; k < KPT; ++k) {
        const int r = rr[k];
        if (r >= L) continue;
        #pragma unroll
        for (int m = 0; m < 3; ++m) {
            const int vv = r + m * L;
            if (vv < P) {
                const int j = vv - shift;
                if (j >= 0 && j < max_len)
                    __stcs(dst + (size_t)j * ROW_F4, v[k]);
                const int j2 = j + P;    // P-wrap generality
                if (j2 >= 0 && j2 < max_len)
                    __stcs(dst + (size_t)j2 * ROW_F4, v[k]);
            }
        }
    }
}

extern "C" void kernel_launch(void* const* d_in, const int* in_sizes, int n_in,
                              void* d_out, int out_size) {
    const float* x       = (const float*)d_in[0];
    const int*   lengths = (const int*)d_in[1];
    float*       out     = (float*)d_out;

    const int B = in_sizes[1];                    // 8
    const int N = in_sizes[0] / (B * C_TOT);      // 16384
    const int max_len = out_size / (B * C_TOT);   // max(lengths)

    dim3 blk(ROW_F4, TY, 1);                      // 480 threads
    dim3 grid((N + TJ - 1) / TJ, 1, B);           // (512,1,8); tail CTAs exit
    rc_scatter_kernel<<<grid, blk>>>((const float4*)x, lengths, (float4*)out,
                                     B, N, max_len);
}